// round 10
// baseline (speedup 1.0000x reference)
#include <cuda_runtime.h>
#include <cstdint>

// Problem constants
#define SN 256        // batch == seq_len
#define EE 1024       // embedding dim
#define HH 10         // hidden dim
#define NG 40         // 4 gates * H
#define TT 50         // tagset size
#define NP (SN*SN)    // 65536 rows (t,b)
#define WG_STRIDE 10340  // (E+H)*H per gate

// Phase A tiling (mma.sync m16n8k8 tf32)
#define BK 32         // k chunk
#define MT 128        // rows per block
#define ATHREADS 128  // 4 warps: each 2 m-tiles x 5 n-tiles
#define NCH (EE/BK)   // 32 chunks
#define AST 36        // padded row stride (floats) -> conflict-free fragment loads
#define A_STAGE_F (MT*AST)   // 4608 floats
#define B_STAGE_F (NG*AST)   // 1440 floats

// smem layout (bytes)
#define SM_STOK 0
#define SM_A    1024
#define SM_B    (SM_A + 2*A_STAGE_F*4)      // 37888
#define SM_TOT  (SM_B + 2*B_STAGE_F*4)      // 49408

// Scratch (no allocations allowed -> device globals)
__device__ float g_base[(size_t)NP * NG];   // x@Wx + bg + theta
__device__ float g_hx[(size_t)NP * HH];     // hx outputs of the scan
__device__ __align__(16) float g_Bt[NCH * NG * BK];  // B transposed per chunk, tf32-rounded

// ---------- helpers ----------
__device__ __forceinline__ void cp16(uint32_t dst, const void* src) {
    asm volatile("cp.async.cg.shared.global [%0], [%1], 16;" :: "r"(dst), "l"(src) : "memory");
}
__device__ __forceinline__ void hmma_tf32(float* d, uint32_t a0, uint32_t a1, uint32_t a2, uint32_t a3,
                                          uint32_t b0, uint32_t b1) {
    asm volatile(
        "mma.sync.aligned.m16n8k8.row.col.f32.tf32.tf32.f32 "
        "{%0,%1,%2,%3}, {%4,%5,%6,%7}, {%8,%9}, {%0,%1,%2,%3};"
        : "+f"(d[0]), "+f"(d[1]), "+f"(d[2]), "+f"(d[3])
        : "r"(a0), "r"(a1), "r"(a2), "r"(a3), "r"(b0), "r"(b1));
}

// =========================================================================
// B pre-transpose + tf32 round: g_Bt[ch][n][k]
// =========================================================================
__global__ __launch_bounds__(256) void prepB_kernel(const float* __restrict__ Wg)
{
    int idx = blockIdx.x * 256 + threadIdx.x;          // 0..40959
    if (idx >= NCH * NG * BK) return;
    int ch = idx / (NG * BK);
    int r  = idx % (NG * BK);
    int n  = r / BK, k = r % BK;
    float v = Wg[(n / HH) * WG_STRIDE + (ch * BK + k) * HH + (n % HH)];
    uint32_t u;
    asm("cvt.rna.tf32.f32 %0, %1;" : "=r"(u) : "f"(v));
    g_Bt[idx] = __uint_as_float(u);
}

// =========================================================================
// Phase A: gathered skinny GEMM on mma.sync tf32 (HMMA).
// 128 rows x 40 cols per CTA. A: k-major smem, stride 36 floats (conflict-
// free fragment loads). B: [n][k] stride 36. Double-buffered cp.async.
// =========================================================================
extern __shared__ char smem_raw[];

__global__ __launch_bounds__(ATHREADS, 4) void phaseA_kernel(
    const int* __restrict__ tok, const float* __restrict__ emb,
    const float* __restrict__ bg, const float* __restrict__ theta)
{
    int*   stok = (int*)(smem_raw + SM_STOK);
    float* sA   = (float*)(smem_raw + SM_A);
    float* sB   = (float*)(smem_raw + SM_B);

    const int tid = threadIdx.x;
    const int rowbase = blockIdx.x * MT;

    if (tid < MT) stok[tid] = tok[rowbase + tid];
    __syncthreads();

    const int wid  = tid >> 5, lane = tid & 31;
    const int g    = lane >> 2, t = lane & 3;
    const int w32  = wid * 32;

    float acc[2][5][4];
#pragma unroll
    for (int m = 0; m < 2; m++)
#pragma unroll
        for (int n = 0; n < 5; n++)
#pragma unroll
            for (int q = 0; q < 4; q++) acc[m][n][q] = 0.f;

    const uint32_t sA_base = (uint32_t)__cvta_generic_to_shared(sA);
    const uint32_t sB_base = (uint32_t)__cvta_generic_to_shared(sB);

    auto issue_chunk = [&](int ch) {
        const int s = ch & 1;
        const uint32_t abase = sA_base + (uint32_t)(s * A_STAGE_F * 4);
#pragma unroll
        for (int it = 0; it < 8; it++) {
            int idx = it * ATHREADS + tid;
            int row = idx >> 3, c = idx & 7;
            cp16(abase + (uint32_t)(row * (AST * 4) + (c << 4)),
                 emb + (size_t)stok[row] * EE + ch * BK + (c << 2));
        }
        const uint32_t bbase = sB_base + (uint32_t)(s * B_STAGE_F * 4);
        const float* bsrc = g_Bt + ch * (NG * BK);
#pragma unroll
        for (int it = 0; it < 3; it++) {
            int i = it * ATHREADS + tid;
            if (i < NG * 8) {
                int n = i >> 3, kq = i & 7;
                cp16(bbase + (uint32_t)(n * (AST * 4) + (kq << 4)), bsrc + (i << 2));
            }
        }
        asm volatile("cp.async.commit_group;" ::: "memory");
    };

    issue_chunk(0);

    for (int ch = 0; ch < NCH; ch++) {
        asm volatile("cp.async.wait_group 0;" ::: "memory");
        __syncthreads();
        if (ch + 1 < NCH) issue_chunk(ch + 1);

        const int s = ch & 1;
        const uint32_t* A = (const uint32_t*)(sA + s * A_STAGE_F);
        const uint32_t* B = (const uint32_t*)(sB + s * B_STAGE_F);
#pragma unroll
        for (int s4 = 0; s4 < 4; s4++) {
            uint32_t b0[5], b1[5];
#pragma unroll
            for (int n = 0; n < 5; n++) {
                const uint32_t* bp = B + (n * 8 + g) * AST + s4 * 8 + t;
                b0[n] = bp[0];
                b1[n] = bp[4];
            }
#pragma unroll
            for (int m = 0; m < 2; m++) {
                const uint32_t* ap = A + (w32 + m * 16 + g) * AST + s4 * 8 + t;
                uint32_t a0 = ap[0];
                uint32_t a2 = ap[4];
                uint32_t a1 = ap[8 * AST];
                uint32_t a3 = ap[8 * AST + 4];
#pragma unroll
                for (int n = 0; n < 5; n++)
                    hmma_tf32(acc[m][n], a0, a1, a2, a3, b0[n], b1[n]);
            }
        }
    }

    // epilogue: add bg + theta, store (D frag: rows g/g+8, cols 2t,2t+1)
    float cbx[5], cby[5];
#pragma unroll
    for (int n = 0; n < 5; n++) {
        int col = n * 8 + 2 * t;
        cbx[n] = bg[col] + theta[col];
        cby[n] = bg[col + 1] + theta[col + 1];
    }
#pragma unroll
    for (int m = 0; m < 2; m++) {
        int row0 = rowbase + w32 + m * 16 + g;
#pragma unroll
        for (int n = 0; n < 5; n++) {
            int col = n * 8 + 2 * t;
            *(float2*)(g_base + (size_t)row0 * NG + col) =
                make_float2(acc[m][n][0] + cbx[n], acc[m][n][1] + cby[n]);
            *(float2*)(g_base + (size_t)(row0 + 8) * NG + col) =
                make_float2(acc[m][n][2] + cbx[n], acc[m][n][3] + cby[n]);
        }
    }
}

// =========================================================================
// Phase B: TWO independent LSTM chains per warp (batch rows 2*blk, 2*blk+1),
// interleaved register streams to hide SHFL/MUFU latency at ~1 warp/SM.
// Per chain: lanes 0-15 gates (f,i), lanes 16-31 gates (g,o); hx/cx
// replicated in both halves; qlayer via serial width-16 shfl_up scan
// (4 registers ride the same shuffle offsets).
// =========================================================================
__global__ __launch_bounds__(32) void phaseB_kernel(const float* __restrict__ Wg)
{
    const int lane = threadIdx.x;
    const int grp  = lane >> 4;          // 0: f,i   1: g,o
    const int l    = lane & 15;
    const bool on  = (l < HH);

    const int gA = grp ? 2 : 0;          // f or g
    const int gB = grp ? 3 : 1;          // i or o

    float wA[HH], wB[HH];                // shared by both chains
#pragma unroll
    for (int j = 0; j < HH; j++) {
        wA[j] = on ? Wg[gA * WG_STRIDE + (EE + j) * HH + l] : 0.f;
        wB[j] = on ? Wg[gB * WG_STRIDE + (EE + j) * HH + l] : 0.f;
    }

    const float sa  = grp ? 2.f : 1.f;
    const float ca  = grp ? 2.f : 1.f;
    const float cbk = grp ? -1.f : 0.f;

    int bq[2] = { blockIdx.x * 2, blockIdx.x * 2 + 1 };
    float hx[2] = {0.f, 0.f}, cx[2] = {0.f, 0.f};
    const float* bpA[2];
    const float* bpB[2];
#pragma unroll
    for (int q = 0; q < 2; q++) {
        bpA[q] = g_base + (size_t)bq[q] * NG + gA * 10 + l;
        bpB[q] = g_base + (size_t)bq[q] * NG + gB * 10 + l;
    }
    const size_t tstride = (size_t)SN * NG;

    float pA[2][4], pB[2][4];
#pragma unroll
    for (int q = 0; q < 2; q++)
#pragma unroll
        for (int i = 0; i < 4; i++) {
            pA[q][i] = on ? bpA[q][i * tstride] : 0.f;
            pB[q][i] = on ? bpB[q][i * tstride] : 0.f;
        }

#pragma unroll 1
    for (int t0 = 0; t0 < SN; t0 += 4) {
        float nA[2][4], nB[2][4];
        if (t0 + 4 < SN) {
#pragma unroll
            for (int q = 0; q < 2; q++)
#pragma unroll
                for (int i = 0; i < 4; i++) {   // 16 batched LDGs -> MLP 16
                    nA[q][i] = on ? bpA[q][(t0 + 4 + i) * tstride] : 0.f;
                    nB[q][i] = on ? bpB[q][(t0 + 4 + i) * tstride] : 0.f;
                }
        } else {
#pragma unroll
            for (int q = 0; q < 2; q++)
#pragma unroll
                for (int i = 0; i < 4; i++) { nA[q][i] = 0.f; nB[q][i] = 0.f; }
        }
#pragma unroll
        for (int tt = 0; tt < 4; tt++) {
            // stage 1: broadcast hx(t-1), dual split dot (both chains)
            float aA0[2], aA1[2], aB0[2], aB1[2];
#pragma unroll
            for (int q = 0; q < 2; q++) {
                aA0[q] = pA[q][tt]; aA1[q] = 0.f;
                aB0[q] = pB[q][tt]; aB1[q] = 0.f;
            }
#pragma unroll
            for (int j = 0; j < HH; j += 2) {
#pragma unroll
                for (int q = 0; q < 2; q++) {
                    float hj0 = __shfl_sync(0xffffffffu, hx[q], j, 16);
                    float hj1 = __shfl_sync(0xffffffffu, hx[q], j + 1, 16);
                    aA0[q] = fmaf(hj0, wA[j], aA0[q]);
                    aA1[q] = fmaf(hj1, wA[j + 1], aA1[q]);
                    aB0[q] = fmaf(hj0, wB[j], aB0[q]);
                    aB1[q] = fmaf(hj1, wB[j + 1], aB1[q]);
                }
            }
            float cA[2], cB[2], dA[2], dB[2];
#pragma unroll
            for (int q = 0; q < 2; q++) {
                cA[q] = __cosf(aA0[q] + aA1[q]);
                cB[q] = __cosf(aB0[q] + aB1[q]);
                dA[q] = (l == 0) ? 1.f : cA[q];
                dB[q] = (l == 0) ? 1.f : cB[q];
            }
            // stage 2: quad-register scan (4 streams share the offsets)
#pragma unroll
            for (int off = 1; off < 16; off <<= 1) {
                float vA0 = __shfl_up_sync(0xffffffffu, dA[0], off, 16);
                float vB0 = __shfl_up_sync(0xffffffffu, dB[0], off, 16);
                float vA1 = __shfl_up_sync(0xffffffffu, dA[1], off, 16);
                float vB1 = __shfl_up_sync(0xffffffffu, dB[1], off, 16);
                if (l >= off) { dA[0] *= vA0; dB[0] *= vB0; dA[1] *= vA1; dB[1] *= vB1; }
            }
            // stage 3: finals + activations + exchange + state update
#pragma unroll
            for (int q = 0; q < 2; q++) {
                float c0A = __shfl_sync(0xffffffffu, cA[q], 0, 16);
                float c0B = __shfl_sync(0xffffffffu, cB[q], 0, 16);
                float q9A = __shfl_sync(0xffffffffu, dA[q], HH - 1, 16);
                float q9B = __shfl_sync(0xffffffffu, dB[q], HH - 1, 16);
                float qA = (l == 0) ? q9A : c0A * dA[q];
                float qB = (l == 0) ? q9B : c0B * dB[q];

                float eA   = __expf(-sa * qA);
                float actA = fmaf(ca, __fdividef(1.f, 1.f + eA), cbk);  // f / g
                float eB   = __expf(-qB);
                float actB = __fdividef(1.f, 1.f + eB);                 // i / o

                float xA = __shfl_xor_sync(0xffffffffu, actA, 16);
                float xB = __shfl_xor_sync(0xffffffffu, actB, 16);
                float f  = grp ? xA   : actA;
                float ii = grp ? xB   : actB;
                float gg = grp ? actA : xA;
                float o  = grp ? actB : xB;

                cx[q] = fmaf(f, cx[q], ii * gg);
                float e2 = __expf(-2.f * cx[q]);
                float th = fmaf(2.f, __fdividef(1.f, 1.f + e2), -1.f);  // tanh(cx)
                hx[q] = o * th;

                if (on && grp == 0)
                    g_hx[((size_t)(t0 + tt) * SN + bq[q]) * HH + l] = hx[q];
            }
        }
#pragma unroll
        for (int q = 0; q < 2; q++)
#pragma unroll
            for (int i = 0; i < 4; i++) { pA[q][i] = nA[q][i]; pB[q][i] = nB[q][i]; }
    }
}

// =========================================================================
// Phase C: logits = hx @ W_out + b_out, then log_softmax over T=50.
// One row per thread, float2 h loads, float2 stores.
// =========================================================================
__global__ __launch_bounds__(128) void phaseC_kernel(
    const float* __restrict__ Wout, const float* __restrict__ bout,
    float* __restrict__ out)
{
    __shared__ float sW[HH * TT];
    __shared__ float sbv[TT];
    const int tid = threadIdx.x;
    for (int i = tid; i < HH * TT; i += 128) sW[i] = Wout[i];
    for (int i = tid; i < TT;      i += 128) sbv[i] = bout[i];
    __syncthreads();

    const int row = blockIdx.x * 128 + tid;
    float h[HH];
#pragma unroll
    for (int j = 0; j < HH; j += 2) {
        float2 v = *(const float2*)(g_hx + (size_t)row * HH + j);
        h[j] = v.x; h[j + 1] = v.y;
    }

    float lg[TT];
#pragma unroll
    for (int c = 0; c < TT; c++) {
        float s = sbv[c];
#pragma unroll
        for (int j = 0; j < HH; j++) s = fmaf(h[j], sW[j * TT + c], s);
        lg[c] = s;
    }
    float m = lg[0];
#pragma unroll
    for (int c = 1; c < TT; c++) m = fmaxf(m, lg[c]);
    float sum = 0.f;
#pragma unroll
    for (int c = 0; c < TT; c++) sum += __expf(lg[c] - m);
    float ls = m + __logf(sum);

    float2* op = (float2*)(out + (size_t)row * TT);
#pragma unroll
    for (int c = 0; c < TT / 2; c++)
        op[c] = make_float2(lg[2 * c] - ls, lg[2 * c + 1] - ls);
}

// =========================================================================
extern "C" void kernel_launch(void* const* d_in, const int* in_sizes, int n_in,
                              void* d_out, int out_size)
{
    const int*   tok   = (const int*)d_in[0];     // sentence (256,256) int32
    const float* emb   = (const float*)d_in[1];   // (V, E)
    const float* Wg    = (const float*)d_in[2];   // (4, E+H, H)
    const float* bg    = (const float*)d_in[3];   // (4, H)
    const float* theta = (const float*)d_in[4];   // (4, H)
    const float* Wout  = (const float*)d_in[5];   // (H, T)
    const float* bout  = (const float*)d_in[6];   // (T)
    float* out = (float*)d_out;                   // (256,256,50) float32

    cudaFuncSetAttribute(phaseA_kernel, cudaFuncAttributeMaxDynamicSharedMemorySize, SM_TOT);

    prepB_kernel<<<(NCH * NG * BK + 255) / 256, 256>>>(Wg);
    phaseA_kernel<<<NP / MT, ATHREADS, SM_TOT>>>(tok, emb, bg, theta);
    phaseB_kernel<<<SN / 2, 32>>>(Wg);
    phaseC_kernel<<<NP / 128, 128>>>(Wout, bout, out);
}

// round 11
// speedup vs baseline: 1.4269x; 1.4269x over previous
#include <cuda_runtime.h>
#include <cstdint>

// Problem constants
#define SN 256        // batch == seq_len
#define EE 1024       // embedding dim
#define HH 10         // hidden dim
#define NG 40         // 4 gates * H
#define TT 50         // tagset size
#define NP (SN*SN)    // 65536 rows (t,b)
#define WG_STRIDE 10340  // (E+H)*H per gate

// Phase A tiling (mma.sync m16n8k8 tf32)
#define BK 32         // k chunk
#define MT 128        // rows per block
#define ATHREADS 128  // 4 warps: each 2 m-tiles x 5 n-tiles
#define NCH (EE/BK)   // 32 chunks
#define AST 36        // padded row stride (floats) -> conflict-free fragment loads
#define A_STAGE_F (MT*AST)   // 4608 floats
#define B_STAGE_F (NG*AST)   // 1440 floats

// smem layout (bytes)
#define SM_STOK 0
#define SM_A    1024
#define SM_B    (SM_A + 2*A_STAGE_F*4)      // 37888
#define SM_TOT  (SM_B + 2*B_STAGE_F*4)      // 49408

// Scratch (no allocations allowed -> device globals)
__device__ float g_base[(size_t)NP * NG];   // x@Wx + bg + theta
__device__ float g_hx[(size_t)NP * HH];     // hx outputs of the scan
__device__ __align__(16) float g_Bt[NCH * NG * BK];  // B transposed per chunk, tf32-rounded

// ---------- helpers ----------
__device__ __forceinline__ void cp16(uint32_t dst, const void* src) {
    asm volatile("cp.async.cg.shared.global [%0], [%1], 16;" :: "r"(dst), "l"(src) : "memory");
}
__device__ __forceinline__ void hmma_tf32(float* d, uint32_t a0, uint32_t a1, uint32_t a2, uint32_t a3,
                                          uint32_t b0, uint32_t b1) {
    asm volatile(
        "mma.sync.aligned.m16n8k8.row.col.f32.tf32.tf32.f32 "
        "{%0,%1,%2,%3}, {%4,%5,%6,%7}, {%8,%9}, {%0,%1,%2,%3};"
        : "+f"(d[0]), "+f"(d[1]), "+f"(d[2]), "+f"(d[3])
        : "r"(a0), "r"(a1), "r"(a2), "r"(a3), "r"(b0), "r"(b1));
}
__device__ __forceinline__ float tanhapx(float x) {
    float y;
    asm("tanh.approx.f32 %0, %1;" : "=f"(y) : "f"(x));
    return y;
}

// =========================================================================
// B pre-transpose + tf32 round: g_Bt[ch][n][k]
// =========================================================================
__global__ __launch_bounds__(256) void prepB_kernel(const float* __restrict__ Wg)
{
    int idx = blockIdx.x * 256 + threadIdx.x;          // 0..40959
    if (idx >= NCH * NG * BK) return;
    int ch = idx / (NG * BK);
    int r  = idx % (NG * BK);
    int n  = r / BK, k = r % BK;
    float v = Wg[(n / HH) * WG_STRIDE + (ch * BK + k) * HH + (n % HH)];
    uint32_t u;
    asm("cvt.rna.tf32.f32 %0, %1;" : "=r"(u) : "f"(v));
    g_Bt[idx] = __uint_as_float(u);
}

// =========================================================================
// Phase A: gathered skinny GEMM on mma.sync tf32 (HMMA).
// 128 rows x 40 cols per CTA. A: k-major smem, stride 36 floats (conflict-
// free fragment loads). B: [n][k] stride 36. Double-buffered cp.async.
// =========================================================================
extern __shared__ char smem_raw[];

__global__ __launch_bounds__(ATHREADS, 4) void phaseA_kernel(
    const int* __restrict__ tok, const float* __restrict__ emb,
    const float* __restrict__ bg, const float* __restrict__ theta)
{
    int*   stok = (int*)(smem_raw + SM_STOK);
    float* sA   = (float*)(smem_raw + SM_A);
    float* sB   = (float*)(smem_raw + SM_B);

    const int tid = threadIdx.x;
    const int rowbase = blockIdx.x * MT;

    if (tid < MT) stok[tid] = tok[rowbase + tid];
    __syncthreads();

    const int wid  = tid >> 5, lane = tid & 31;
    const int g    = lane >> 2, t = lane & 3;
    const int w32  = wid * 32;

    float acc[2][5][4];
#pragma unroll
    for (int m = 0; m < 2; m++)
#pragma unroll
        for (int n = 0; n < 5; n++)
#pragma unroll
            for (int q = 0; q < 4; q++) acc[m][n][q] = 0.f;

    const uint32_t sA_base = (uint32_t)__cvta_generic_to_shared(sA);
    const uint32_t sB_base = (uint32_t)__cvta_generic_to_shared(sB);

    auto issue_chunk = [&](int ch) {
        const int s = ch & 1;
        const uint32_t abase = sA_base + (uint32_t)(s * A_STAGE_F * 4);
#pragma unroll
        for (int it = 0; it < 8; it++) {
            int idx = it * ATHREADS + tid;
            int row = idx >> 3, c = idx & 7;
            cp16(abase + (uint32_t)(row * (AST * 4) + (c << 4)),
                 emb + (size_t)stok[row] * EE + ch * BK + (c << 2));
        }
        const uint32_t bbase = sB_base + (uint32_t)(s * B_STAGE_F * 4);
        const float* bsrc = g_Bt + ch * (NG * BK);
#pragma unroll
        for (int it = 0; it < 3; it++) {
            int i = it * ATHREADS + tid;
            if (i < NG * 8) {
                int n = i >> 3, kq = i & 7;
                cp16(bbase + (uint32_t)(n * (AST * 4) + (kq << 4)), bsrc + (i << 2));
            }
        }
        asm volatile("cp.async.commit_group;" ::: "memory");
    };

    issue_chunk(0);

    for (int ch = 0; ch < NCH; ch++) {
        asm volatile("cp.async.wait_group 0;" ::: "memory");
        __syncthreads();
        if (ch + 1 < NCH) issue_chunk(ch + 1);

        const int s = ch & 1;
        const uint32_t* A = (const uint32_t*)(sA + s * A_STAGE_F);
        const uint32_t* B = (const uint32_t*)(sB + s * B_STAGE_F);
#pragma unroll
        for (int s4 = 0; s4 < 4; s4++) {
            uint32_t b0[5], b1[5];
#pragma unroll
            for (int n = 0; n < 5; n++) {
                const uint32_t* bp = B + (n * 8 + g) * AST + s4 * 8 + t;
                b0[n] = bp[0];
                b1[n] = bp[4];
            }
#pragma unroll
            for (int m = 0; m < 2; m++) {
                const uint32_t* ap = A + (w32 + m * 16 + g) * AST + s4 * 8 + t;
                uint32_t a0 = ap[0];
                uint32_t a2 = ap[4];
                uint32_t a1 = ap[8 * AST];
                uint32_t a3 = ap[8 * AST + 4];
#pragma unroll
                for (int n = 0; n < 5; n++)
                    hmma_tf32(acc[m][n], a0, a1, a2, a3, b0[n], b1[n]);
            }
        }
    }

    // epilogue: add bg + theta, store (D frag: rows g/g+8, cols 2t,2t+1)
    float cbx[5], cby[5];
#pragma unroll
    for (int n = 0; n < 5; n++) {
        int col = n * 8 + 2 * t;
        cbx[n] = bg[col] + theta[col];
        cby[n] = bg[col + 1] + theta[col + 1];
    }
#pragma unroll
    for (int m = 0; m < 2; m++) {
        int row0 = rowbase + w32 + m * 16 + g;
#pragma unroll
        for (int n = 0; n < 5; n++) {
            int col = n * 8 + 2 * t;
            *(float2*)(g_base + (size_t)row0 * NG + col) =
                make_float2(acc[m][n][0] + cbx[n], acc[m][n][1] + cby[n]);
            *(float2*)(g_base + (size_t)(row0 + 8) * NG + col) =
                make_float2(acc[m][n][2] + cbx[n], acc[m][n][3] + cby[n]);
        }
    }
}

// =========================================================================
// Phase B: one LSTM chain per warp (R6 structure — best measured).
// Lanes 0-15: gates (f,i); lanes 16-31: gates (g,o); hx/cx replicated.
// Activations via tanh.approx (sigmoid = 0.5 + 0.5*tanh(x/2)) — one MUFU
// op replacing exp+div chains on the critical path.
// =========================================================================
__global__ __launch_bounds__(32) void phaseB_kernel(const float* __restrict__ Wg)
{
    const int lane = threadIdx.x;
    const int grp  = lane >> 4;          // 0: f,i   1: g,o
    const int l    = lane & 15;
    const int b    = blockIdx.x;
    const bool on  = (l < HH);

    const int gA = grp ? 2 : 0;          // f or g
    const int gB = grp ? 3 : 1;          // i or o

    float wA[HH], wB[HH];
#pragma unroll
    for (int j = 0; j < HH; j++) {
        wA[j] = on ? Wg[gA * WG_STRIDE + (EE + j) * HH + l] : 0.f;
        wB[j] = on ? Wg[gB * WG_STRIDE + (EE + j) * HH + l] : 0.f;
    }

    // gate A activation: grp0 sigmoid -> 0.5 + 0.5*tanh(0.5x); grp1 tanh -> tanh(x)
    const float ssA = grp ? 1.f : 0.5f;   // input scale
    const float kA  = grp ? 1.f : 0.5f;   // output scale
    const float bAc = grp ? 0.f : 0.5f;   // output bias

    float hx = 0.f, cx = 0.f;
    const float* bpA = g_base + (size_t)b * NG + gA * 10 + l;
    const float* bpB = g_base + (size_t)b * NG + gB * 10 + l;
    const size_t tstride = (size_t)SN * NG;

    float pA[4], pB[4];
#pragma unroll
    for (int i = 0; i < 4; i++) {
        pA[i] = on ? bpA[i * tstride] : 0.f;
        pB[i] = on ? bpB[i * tstride] : 0.f;
    }

#pragma unroll 1
    for (int t0 = 0; t0 < SN; t0 += 4) {
        float nA[4], nB[4];
        if (t0 + 4 < SN) {
#pragma unroll
            for (int i = 0; i < 4; i++) {       // batch 8 LDGs -> MLP 8
                nA[i] = on ? bpA[(t0 + 4 + i) * tstride] : 0.f;
                nB[i] = on ? bpB[(t0 + 4 + i) * tstride] : 0.f;
            }
        } else {
#pragma unroll
            for (int i = 0; i < 4; i++) { nA[i] = 0.f; nB[i] = 0.f; }
        }
#pragma unroll
        for (int tt = 0; tt < 4; tt++) {
            // broadcast hx(t-1); split dot into two parallel chains
            float aA0 = pA[tt], aA1 = 0.f, aB0 = pB[tt], aB1 = 0.f;
#pragma unroll
            for (int j = 0; j < HH; j += 2) {
                float hj0 = __shfl_sync(0xffffffffu, hx, j, 16);
                float hj1 = __shfl_sync(0xffffffffu, hx, j + 1, 16);
                aA0 = fmaf(hj0, wA[j], aA0);
                aA1 = fmaf(hj1, wA[j + 1], aA1);
                aB0 = fmaf(hj0, wB[j], aB0);
                aB1 = fmaf(hj1, wB[j + 1], aB1);
            }
            float aA = aA0 + aA1, aB = aB0 + aB1;

            // qlayer: dual-register serial width-16 scan
            float cA = __cosf(aA), cB = __cosf(aB);
            float dA = (l == 0) ? 1.f : cA;
            float dB = (l == 0) ? 1.f : cB;
#pragma unroll
            for (int off = 1; off < 16; off <<= 1) {
                float vA = __shfl_up_sync(0xffffffffu, dA, off, 16);
                float vB = __shfl_up_sync(0xffffffffu, dB, off, 16);
                if (l >= off) { dA *= vA; dB *= vB; }
            }
            float c0A = __shfl_sync(0xffffffffu, cA, 0, 16);
            float c0B = __shfl_sync(0xffffffffu, cB, 0, 16);
            float q9A = __shfl_sync(0xffffffffu, dA, HH - 1, 16);
            float q9B = __shfl_sync(0xffffffffu, dB, HH - 1, 16);
            float qA = (l == 0) ? q9A : c0A * dA;
            float qB = (l == 0) ? q9B : c0B * dB;

            // activations via tanh.approx
            float actA = fmaf(kA, tanhapx(ssA * qA), bAc);          // f / g
            float actB = fmaf(0.5f, tanhapx(0.5f * qB), 0.5f);      // i / o

            // exchange halves: grp0 gets (g,o), grp1 gets (f,i)
            float xA = __shfl_xor_sync(0xffffffffu, actA, 16);
            float xB = __shfl_xor_sync(0xffffffffu, actB, 16);
            float f  = grp ? xA   : actA;
            float ii = grp ? xB   : actB;
            float gg = grp ? actA : xA;
            float o  = grp ? actB : xB;

            cx = fmaf(f, cx, ii * gg);
            hx = o * tanhapx(cx);

            if (on && grp == 0) g_hx[((size_t)(t0 + tt) * SN + b) * HH + l] = hx;
        }
#pragma unroll
        for (int i = 0; i < 4; i++) { pA[i] = nA[i]; pB[i] = nB[i]; }
    }
}

// =========================================================================
// Phase C: logits = hx @ W_out + b_out, then log_softmax over T=50.
// One row per thread, float2 h loads, float2 stores.
// =========================================================================
__global__ __launch_bounds__(128) void phaseC_kernel(
    const float* __restrict__ Wout, const float* __restrict__ bout,
    float* __restrict__ out)
{
    __shared__ float sW[HH * TT];
    __shared__ float sbv[TT];
    const int tid = threadIdx.x;
    for (int i = tid; i < HH * TT; i += 128) sW[i] = Wout[i];
    for (int i = tid; i < TT;      i += 128) sbv[i] = bout[i];
    __syncthreads();

    const int row = blockIdx.x * 128 + tid;
    float h[HH];
#pragma unroll
    for (int j = 0; j < HH; j += 2) {
        float2 v = *(const float2*)(g_hx + (size_t)row * HH + j);
        h[j] = v.x; h[j + 1] = v.y;
    }

    float lg[TT];
#pragma unroll
    for (int c = 0; c < TT; c++) {
        float s = sbv[c];
#pragma unroll
        for (int j = 0; j < HH; j++) s = fmaf(h[j], sW[j * TT + c], s);
        lg[c] = s;
    }
    float m = lg[0];
#pragma unroll
    for (int c = 1; c < TT; c++) m = fmaxf(m, lg[c]);
    float sum = 0.f;
#pragma unroll
    for (int c = 0; c < TT; c++) sum += __expf(lg[c] - m);
    float ls = m + __logf(sum);

    float2* op = (float2*)(out + (size_t)row * TT);
#pragma unroll
    for (int c = 0; c < TT / 2; c++)
        op[c] = make_float2(lg[2 * c] - ls, lg[2 * c + 1] - ls);
}

// =========================================================================
extern "C" void kernel_launch(void* const* d_in, const int* in_sizes, int n_in,
                              void* d_out, int out_size)
{
    const int*   tok   = (const int*)d_in[0];     // sentence (256,256) int32
    const float* emb   = (const float*)d_in[1];   // (V, E)
    const float* Wg    = (const float*)d_in[2];   // (4, E+H, H)
    const float* bg    = (const float*)d_in[3];   // (4, H)
    const float* theta = (const float*)d_in[4];   // (4, H)
    const float* Wout  = (const float*)d_in[5];   // (H, T)
    const float* bout  = (const float*)d_in[6];   // (T)
    float* out = (float*)d_out;                   // (256,256,50) float32

    cudaFuncSetAttribute(phaseA_kernel, cudaFuncAttributeMaxDynamicSharedMemorySize, SM_TOT);

    prepB_kernel<<<(NCH * NG * BK + 255) / 256, 256>>>(Wg);
    phaseA_kernel<<<NP / MT, ATHREADS, SM_TOT>>>(tok, emb, bg, theta);
    phaseB_kernel<<<SN, 32>>>(Wg);
    phaseC_kernel<<<NP / 128, 128>>>(Wout, bout, out);
}